// round 1
// baseline (speedup 1.0000x reference)
#include <cuda_runtime.h>
#include <cuda_bf16.h>
#include <math.h>

// Problem constants
#define B_  2
#define T_  2048
#define E_  2048
#define H_  32
#define HKV_ 8
#define D_  64
#define G_  4        // H/HKV
#define BT_ (B_*T_)  // 4096

// ---------------------------------------------------------------------------
// Scratch (static device globals — allocation-free rule)
// ---------------------------------------------------------------------------
__device__ float g_Q[BT_ * H_ * D_];    // 4096 x 2048
__device__ float g_K[BT_ * HKV_ * D_];  // 4096 x 512
__device__ float g_V[BT_ * HKV_ * D_];  // 4096 x 512
__device__ float g_Y[BT_ * H_ * D_];    // 4096 x 2048

// ---------------------------------------------------------------------------
// Generic fp32 GEMM: C[M,N] = A[M,K] @ B[K,N], all row-major.
// M % 64 == 0, N % 64 == 0, K % 16 == 0.
// 64x64 tile, BK=16, 256 threads, 4x4 per-thread register tile.
// ---------------------------------------------------------------------------
__global__ __launch_bounds__(256)
void gemm_kernel(float* __restrict__ C, const float* __restrict__ A,
                 const float* __restrict__ Bm, int M, int N, int K) {
    __shared__ float As[16][64];   // [k][m]
    __shared__ float Bs[16][64];   // [k][n]

    const int tid = threadIdx.x;
    const int bm = blockIdx.y * 64;
    const int bn = blockIdx.x * 64;
    const int tx = tid & 15;        // 0..15 -> n
    const int ty = tid >> 4;        // 0..15 -> m

    // A-tile load mapping: 64 rows x 16 cols, one float4 per thread
    const int arow = tid >> 2;      // 0..63
    const int ac4  = tid & 3;       // 0..3  (col = ac4*4)
    // B-tile load mapping: 16 rows x 64 cols
    const int brow = tid >> 4;      // 0..15
    const int bc4  = tid & 15;      // 0..15 (col = bc4*4)

    float acc[4][4];
#pragma unroll
    for (int i = 0; i < 4; ++i)
#pragma unroll
        for (int j = 0; j < 4; ++j) acc[i][j] = 0.0f;

    for (int k0 = 0; k0 < K; k0 += 16) {
        float4 av = *(const float4*)&A[(size_t)(bm + arow) * K + k0 + (ac4 << 2)];
        float4 bv = *(const float4*)&Bm[(size_t)(k0 + brow) * N + bn + (bc4 << 2)];

        __syncthreads();   // protect smem from previous iteration's readers
        As[(ac4 << 2) + 0][arow] = av.x;
        As[(ac4 << 2) + 1][arow] = av.y;
        As[(ac4 << 2) + 2][arow] = av.z;
        As[(ac4 << 2) + 3][arow] = av.w;
        *(float4*)&Bs[brow][bc4 << 2] = bv;
        __syncthreads();

#pragma unroll
        for (int kk = 0; kk < 16; ++kk) {
            float4 ra = *(const float4*)&As[kk][ty << 2];
            float4 rb = *(const float4*)&Bs[kk][tx << 2];
            float a0 = ra.x, a1 = ra.y, a2 = ra.z, a3 = ra.w;
            float b0 = rb.x, b1 = rb.y, b2 = rb.z, b3 = rb.w;
            acc[0][0] += a0 * b0; acc[0][1] += a0 * b1; acc[0][2] += a0 * b2; acc[0][3] += a0 * b3;
            acc[1][0] += a1 * b0; acc[1][1] += a1 * b1; acc[1][2] += a1 * b2; acc[1][3] += a1 * b3;
            acc[2][0] += a2 * b0; acc[2][1] += a2 * b1; acc[2][2] += a2 * b2; acc[2][3] += a2 * b3;
            acc[3][0] += a3 * b0; acc[3][1] += a3 * b1; acc[3][2] += a3 * b2; acc[3][3] += a3 * b3;
        }
    }

#pragma unroll
    for (int i = 0; i < 4; ++i) {
        float4 v = make_float4(acc[i][0], acc[i][1], acc[i][2], acc[i][3]);
        *(float4*)&C[(size_t)(bm + (ty << 2) + i) * N + bn + (tx << 2)] = v;
    }
}

// ---------------------------------------------------------------------------
// RoPE (in place). buf layout: [(b*T+t) * nh*64 + h*64 + d]
// One thread per (b,t,h,i), i in [0,32): rotate pair (i, i+32).
// ---------------------------------------------------------------------------
__global__ __launch_bounds__(256)
void rope_kernel(float* __restrict__ buf, int nh) {
    int idx = blockIdx.x * blockDim.x + threadIdx.x;
    int total = B_ * T_ * nh * 32;
    if (idx >= total) return;
    int i = idx & 31;
    int h = (idx >> 5) % nh;
    int t = (idx / (32 * nh)) % T_;
    int b = idx / (32 * nh * T_);

    // inv_freq = 10000^(-2i/64) = exp(-(i/32)*ln(10000))
    float inv_freq = expf(-(float)i * (9.210340371976184f / 32.0f));
    float ang = (float)t * inv_freq;
    float c = cosf(ang), s = sinf(ang);

    size_t off = ((size_t)(b * T_ + t) * nh + h) * 64;
    float x1 = buf[off + i];
    float x2 = buf[off + 32 + i];
    buf[off + i]      = x1 * c - x2 * s;
    buf[off + 32 + i] = x2 * c + x1 * s;
}

// ---------------------------------------------------------------------------
// Flash-style causal attention, fp32.
// Grid: (T/64, H, B), Block: 64 threads. Thread r owns query row qt*64+r.
// ---------------------------------------------------------------------------
__global__ __launch_bounds__(64)
void attn_kernel(float* __restrict__ Y, const float* __restrict__ Q,
                 const float* __restrict__ K, const float* __restrict__ V) {
    __shared__ float Ksh[64][64];
    __shared__ float Vsh[64][64];
    __shared__ float Ssh[64][64];  // [s][r] lane-major -> conflict-free

    const int r  = threadIdx.x;           // 0..63
    const int qt = blockIdx.x;
    const int h  = blockIdx.y;
    const int b  = blockIdx.z;
    const int kh = h >> 2;                // G = 4
    const int qi = qt * 64 + r;

    // Load query row into registers
    float q[64];
    {
        const float4* q4 = (const float4*)(Q + ((size_t)(b * T_ + qi) * H_ + h) * 64);
#pragma unroll
        for (int i = 0; i < 16; ++i) {
            float4 v = q4[i];
            q[4 * i + 0] = v.x; q[4 * i + 1] = v.y; q[4 * i + 2] = v.z; q[4 * i + 3] = v.w;
        }
    }

    float o[64];
#pragma unroll
    for (int d = 0; d < 64; ++d) o[d] = 0.0f;
    float m = -1e30f, l = 0.0f;
    const float scale = 0.125f;   // 1/sqrt(64)

    for (int j = 0; j <= qt; ++j) {
        const float* Kt = K + (size_t)(b * T_ + j * 64) * (HKV_ * D_) + kh * 64;
        const float* Vt = V + (size_t)(b * T_ + j * 64) * (HKV_ * D_) + kh * 64;

        __syncthreads();  // previous tile's consumers done
#pragma unroll
        for (int i = 0; i < 16; ++i) {
            int p = r + i * 64;
            int row = p >> 4, c4 = p & 15;
            *(float4*)&Ksh[row][c4 << 2] = *(const float4*)(Kt + (size_t)row * (HKV_ * D_) + (c4 << 2));
            *(float4*)&Vsh[row][c4 << 2] = *(const float4*)(Vt + (size_t)row * (HKV_ * D_) + (c4 << 2));
        }
        __syncthreads();

        const int smax = (j == qt) ? (r + 1) : 64;   // causal: s_local <= r on diagonal tile
        float tmax = -1e30f;

        // Pass A: scores -> Ssh, track tile max
        for (int s = 0; s < 64; ++s) {
            float a0 = 0.f, a1 = 0.f, a2 = 0.f, a3 = 0.f;
            float a4 = 0.f, a5 = 0.f, a6 = 0.f, a7 = 0.f;
#pragma unroll
            for (int dd = 0; dd < 8; ++dd) {
                a0 += q[dd * 8 + 0] * Ksh[s][dd * 8 + 0];
                a1 += q[dd * 8 + 1] * Ksh[s][dd * 8 + 1];
                a2 += q[dd * 8 + 2] * Ksh[s][dd * 8 + 2];
                a3 += q[dd * 8 + 3] * Ksh[s][dd * 8 + 3];
                a4 += q[dd * 8 + 4] * Ksh[s][dd * 8 + 4];
                a5 += q[dd * 8 + 5] * Ksh[s][dd * 8 + 5];
                a6 += q[dd * 8 + 6] * Ksh[s][dd * 8 + 6];
                a7 += q[dd * 8 + 7] * Ksh[s][dd * 8 + 7];
            }
            float sc = (((a0 + a1) + (a2 + a3)) + ((a4 + a5) + (a6 + a7))) * scale;
            if (s >= smax) sc = -1e30f;
            Ssh[s][r] = sc;
            tmax = fmaxf(tmax, sc);
        }

        // Online softmax rescale
        float mnew = fmaxf(m, tmax);
        float corr = __expf(m - mnew);
        l *= corr;
#pragma unroll
        for (int d = 0; d < 64; ++d) o[d] *= corr;

        // Pass B: accumulate P @ V
        for (int s = 0; s < 64; ++s) {
            float p = __expf(Ssh[s][r] - mnew);
            l += p;
#pragma unroll
            for (int d = 0; d < 64; ++d) o[d] += p * Vsh[s][d];
        }
        m = mnew;
    }

    float inv = 1.0f / l;
    float* yrow = Y + ((size_t)(b * T_ + qi) * H_ + h) * 64;
#pragma unroll
    for (int i = 0; i < 16; ++i) {
        float4 v = make_float4(o[4 * i + 0] * inv, o[4 * i + 1] * inv,
                               o[4 * i + 2] * inv, o[4 * i + 3] * inv);
        ((float4*)yrow)[i] = v;
    }
}

// ---------------------------------------------------------------------------
// kernel_launch
// Inputs: x[B,T,E], Wq[E,H*D], Wk[E,HKV*D], Wv[E,HKV*D], Wo[E,E]; out fp32 [B,T,E]
// ---------------------------------------------------------------------------
extern "C" void kernel_launch(void* const* d_in, const int* in_sizes, int n_in,
                              void* d_out, int out_size) {
    const float* x  = (const float*)d_in[0];
    const float* Wq = (const float*)d_in[1];
    const float* Wk = (const float*)d_in[2];
    const float* Wv = (const float*)d_in[3];
    const float* Wo = (const float*)d_in[4];
    float* out = (float*)d_out;

    float *pQ, *pK, *pV, *pY;
    cudaGetSymbolAddress((void**)&pQ, g_Q);
    cudaGetSymbolAddress((void**)&pK, g_K);
    cudaGetSymbolAddress((void**)&pV, g_V);
    cudaGetSymbolAddress((void**)&pY, g_Y);

    // QKV projections
    gemm_kernel<<<dim3((H_ * D_) / 64, BT_ / 64), 256>>>(pQ, x, Wq, BT_, H_ * D_, E_);
    gemm_kernel<<<dim3((HKV_ * D_) / 64, BT_ / 64), 256>>>(pK, x, Wk, BT_, HKV_ * D_, E_);
    gemm_kernel<<<dim3((HKV_ * D_) / 64, BT_ / 64), 256>>>(pV, x, Wv, BT_, HKV_ * D_, E_);

    // RoPE on Q and K
    {
        int nq = B_ * T_ * H_ * 32;
        rope_kernel<<<(nq + 255) / 256, 256>>>(pQ, H_);
        int nk = B_ * T_ * HKV_ * 32;
        rope_kernel<<<(nk + 255) / 256, 256>>>(pK, HKV_);
    }

    // Attention
    attn_kernel<<<dim3(T_ / 64, H_, B_), 64>>>(pY, pQ, pK, pV);

    // Output projection
    gemm_kernel<<<dim3(E_ / 64, BT_ / 64), 256>>>(out, pY, Wo, BT_, E_, E_);
}

// round 3
// speedup vs baseline: 1.5577x; 1.5577x over previous
#include <cuda_runtime.h>
#include <cuda_bf16.h>
#include <cstdint>
#include <math.h>

// Problem constants
#define B_  2
#define T_  2048
#define E_  2048
#define H_  32
#define HKV_ 8
#define D_  64
#define BT_ (B_*T_)  // 4096

// ---------------------------------------------------------------------------
// Scratch (static device globals — allocation-free rule)
// ---------------------------------------------------------------------------
__device__ float g_Q[BT_ * H_ * D_];
__device__ float g_K[BT_ * HKV_ * D_];
__device__ float g_V[BT_ * HKV_ * D_];
__device__ float g_Y[BT_ * H_ * D_];

__device__ __nv_bfloat16 g_xh[BT_ * E_],  g_xl[BT_ * E_];
__device__ __nv_bfloat16 g_Yh[BT_ * E_],  g_Yl[BT_ * E_];
// Transposed weights [N, K] split hi/lo
__device__ __nv_bfloat16 g_Wqh[E_ * H_ * D_],   g_Wql[E_ * H_ * D_];
__device__ __nv_bfloat16 g_Wkh[E_ * HKV_ * D_], g_Wkl[E_ * HKV_ * D_];
__device__ __nv_bfloat16 g_Wvh[E_ * HKV_ * D_], g_Wvl[E_ * HKV_ * D_];
__device__ __nv_bfloat16 g_Woh[E_ * E_],        g_Wol[E_ * E_];

// ---------------------------------------------------------------------------
// PTX helpers (sm_80+ path: mma.sync / ldmatrix / cp.async)
// ---------------------------------------------------------------------------
__device__ __forceinline__ uint32_t smem_u32(const void* p) {
    uint32_t a;
    asm("{ .reg .u64 t; cvta.to.shared.u64 t, %1; cvt.u32.u64 %0, t; }" : "=r"(a) : "l"(p));
    return a;
}

__device__ __forceinline__ void ldmx4(uint32_t* r, uint32_t addr) {
    asm volatile("ldmatrix.sync.aligned.m8n8.x4.shared.b16 {%0,%1,%2,%3}, [%4];"
                 : "=r"(r[0]), "=r"(r[1]), "=r"(r[2]), "=r"(r[3]) : "r"(addr));
}

__device__ __forceinline__ void mma_bf16(float* acc, const uint32_t* a, const uint32_t b0,
                                         const uint32_t b1) {
    asm volatile(
        "mma.sync.aligned.m16n8k16.row.col.f32.bf16.bf16.f32 "
        "{%0,%1,%2,%3}, {%4,%5,%6,%7}, {%8,%9}, {%0,%1,%2,%3};"
        : "+f"(acc[0]), "+f"(acc[1]), "+f"(acc[2]), "+f"(acc[3])
        : "r"(a[0]), "r"(a[1]), "r"(a[2]), "r"(a[3]), "r"(b0), "r"(b1));
}

__device__ __forceinline__ void cp_async16(uint32_t saddr, const void* gaddr) {
    asm volatile("cp.async.cg.shared.global [%0], [%1], 16;" :: "r"(saddr), "l"(gaddr));
}
#define CP_COMMIT() asm volatile("cp.async.commit_group;" ::: "memory")
#define CP_WAIT(n)  asm volatile("cp.async.wait_group %0;" :: "n"(n) : "memory")

// ---------------------------------------------------------------------------
// bf16x3 split-precision GEMM via mma.sync.
// C[M,N](fp32) = Ah·Bh^T + Ah·Bl^T + Al·Bh^T;  A[M,K], B[N,K] bf16 K-major.
// 128x128 CTA tile, BK=32, 256 threads, double-buffered cp.async pipeline.
// smem region layout: 128 rows x 80B (64B data + 16B pad, conflict-free ldmatrix)
// ---------------------------------------------------------------------------
#define ROWB   80
#define REGB   (128 * ROWB)          // 10240 bytes per region
#define BUFB   (4 * REGB)            // Ah, Al, Bh, Bl
#define GEMM_SMEM_TOTAL (2 * BUFB)   // 81920

__device__ __forceinline__ void issue_buf(uint32_t sbuf,
                                          const __nv_bfloat16* ah, const __nv_bfloat16* al,
                                          const __nv_bfloat16* bh, const __nv_bfloat16* bl,
                                          int K, int tid) {
    const __nv_bfloat16* srcs[4] = {ah, al, bh, bl};
#pragma unroll
    for (int reg = 0; reg < 4; ++reg) {
        const __nv_bfloat16* s = srcs[reg];
        uint32_t sr = sbuf + reg * REGB;
#pragma unroll
        for (int j = 0; j < 2; ++j) {
            int c = tid + j * 256;           // 0..511
            int row = c >> 2, part = c & 3;
            cp_async16(sr + row * ROWB + part * 16, s + (size_t)row * K + part * 8);
        }
    }
}

__global__ __launch_bounds__(256)
void gemm3_kernel(float* __restrict__ C,
                  const __nv_bfloat16* __restrict__ Ah, const __nv_bfloat16* __restrict__ Al,
                  const __nv_bfloat16* __restrict__ Bh, const __nv_bfloat16* __restrict__ Bl,
                  int M, int N, int K) {
    extern __shared__ char smem[];
    const uint32_t sbase = smem_u32(smem);
    const int tid = threadIdx.x;
    const int wid = tid >> 5, lane = tid & 31;
    const int warp_m = wid >> 2;          // 0..1 -> 64-row slab
    const int warp_n = wid & 3;           // 0..3 -> 32-col slab
    const int bm = blockIdx.y * 128, bn = blockIdx.x * 128;

    const __nv_bfloat16* pAh = Ah + (size_t)bm * K;
    const __nv_bfloat16* pAl = Al + (size_t)bm * K;
    const __nv_bfloat16* pBh = Bh + (size_t)bn * K;
    const __nv_bfloat16* pBl = Bl + (size_t)bn * K;

    float acc[4][4][4];
#pragma unroll
    for (int i = 0; i < 4; ++i)
#pragma unroll
        for (int j = 0; j < 4; ++j)
#pragma unroll
            for (int k = 0; k < 4; ++k) acc[i][j][k] = 0.0f;

    const int NIT = K / 32;

    // ldmatrix address components (constant per thread)
    const uint32_t a_row = warp_m * 64 + (lane & 15);
    const uint32_t a_coff = (lane >> 4) * 16;
    const uint32_t b_rowbase = warp_n * 32 + (lane & 15);
    const uint32_t b_coff = (lane >> 4) * 16;

    issue_buf(sbase, pAh, pAl, pBh, pBl, K, tid);
    CP_COMMIT();

    for (int it = 0; it < NIT; ++it) {
        const uint32_t sbuf = sbase + (it & 1) * BUFB;
        if (it + 1 < NIT) {
            issue_buf(sbase + ((it + 1) & 1) * BUFB,
                      pAh + (it + 1) * 32, pAl + (it + 1) * 32,
                      pBh + (it + 1) * 32, pBl + (it + 1) * 32, K, tid);
            CP_COMMIT();
            CP_WAIT(1);
        } else {
            CP_WAIT(0);
        }
        __syncthreads();

        const uint32_t sAh = sbuf, sAl = sbuf + REGB;
        const uint32_t sBh = sbuf + 2 * REGB, sBl = sbuf + 3 * REGB;

#pragma unroll
        for (int ks = 0; ks < 2; ++ks) {
            const uint32_t kb = ks * 32;
            // B fragments: x4 covers two n8 blocks. p=0 -> n[0,16), p=1 -> n[16,32)
            uint32_t bh[8], bl[8];
#pragma unroll
            for (int p = 0; p < 2; ++p) {
                uint32_t ba = (b_rowbase + p * 16) * ROWB + kb + b_coff;
                ldmx4(&bh[p * 4], sBh + ba);
                ldmx4(&bl[p * 4], sBl + ba);
            }
#pragma unroll
            for (int mi = 0; mi < 4; ++mi) {
                uint32_t aa = (a_row + mi * 16) * ROWB + kb + a_coff;
                uint32_t ah[4], al[4];
                ldmx4(ah, sAh + aa);
                ldmx4(al, sAl + aa);
#pragma unroll
                for (int ni = 0; ni < 4; ++ni) {
                    const int p = ni >> 1, q = ni & 1;
                    uint32_t b0h = bh[p * 4 + q], b1h = bh[p * 4 + q + 2];
                    uint32_t b0l = bl[p * 4 + q], b1l = bl[p * 4 + q + 2];
                    mma_bf16(acc[mi][ni], ah, b0h, b1h);
                    mma_bf16(acc[mi][ni], ah, b0l, b1l);
                    mma_bf16(acc[mi][ni], al, b0h, b1h);
                }
            }
        }
        __syncthreads();
    }

    // Epilogue: m16n8 frag layout -> rows lane/4 (+8), cols 2*(lane%4)
    const int rbase = bm + warp_m * 64 + (lane >> 2);
    const int cbase = bn + warp_n * 32 + (lane & 3) * 2;
#pragma unroll
    for (int mi = 0; mi < 4; ++mi) {
#pragma unroll
        for (int ni = 0; ni < 4; ++ni) {
            float* c0 = C + (size_t)(rbase + mi * 16) * N + cbase + ni * 8;
            float* c1 = C + (size_t)(rbase + mi * 16 + 8) * N + cbase + ni * 8;
            *(float2*)c0 = make_float2(acc[mi][ni][0], acc[mi][ni][1]);
            *(float2*)c1 = make_float2(acc[mi][ni][2], acc[mi][ni][3]);
        }
    }
}

// ---------------------------------------------------------------------------
// fp32 -> bf16 hi/lo split
// ---------------------------------------------------------------------------
__global__ __launch_bounds__(256)
void split_kernel(const float* __restrict__ in, __nv_bfloat16* __restrict__ hi,
                  __nv_bfloat16* __restrict__ lo, int n) {
    int i = blockIdx.x * blockDim.x + threadIdx.x;
    if (i >= n) return;
    float v = in[i];
    __nv_bfloat16 h = __float2bfloat16(v);
    hi[i] = h;
    lo[i] = __float2bfloat16(v - __bfloat162float(h));
}

// ---------------------------------------------------------------------------
// Transpose + split: W[K,N] fp32 -> Th/Tl[N,K] bf16
// ---------------------------------------------------------------------------
__global__ __launch_bounds__(256)
void tsplit_kernel(const float* __restrict__ W, __nv_bfloat16* __restrict__ Th,
                   __nv_bfloat16* __restrict__ Tl, int K, int N) {
    __shared__ float t[32][33];
    const int tx = threadIdx.x, ty = threadIdx.y;   // block (32, 8)
    const int n0 = blockIdx.x * 32, k0 = blockIdx.y * 32;
#pragma unroll
    for (int i = 0; i < 4; ++i)
        t[ty + i * 8][tx] = W[(size_t)(k0 + ty + i * 8) * N + n0 + tx];
    __syncthreads();
#pragma unroll
    for (int i = 0; i < 4; ++i) {
        float v = t[tx][ty + i * 8];
        __nv_bfloat16 h = __float2bfloat16(v);
        size_t o = (size_t)(n0 + ty + i * 8) * K + k0 + tx;
        Th[o] = h;
        Tl[o] = __float2bfloat16(v - __bfloat162float(h));
    }
}

// ---------------------------------------------------------------------------
// RoPE (in place)
// ---------------------------------------------------------------------------
__global__ __launch_bounds__(256)
void rope_kernel(float* __restrict__ buf, int nh) {
    int idx = blockIdx.x * blockDim.x + threadIdx.x;
    int total = B_ * T_ * nh * 32;
    if (idx >= total) return;
    int i = idx & 31;
    int h = (idx >> 5) % nh;
    int t = (idx / (32 * nh)) % T_;
    int b = idx / (32 * nh * T_);

    float inv_freq = expf(-(float)i * (9.210340371976184f / 32.0f));
    float ang = (float)t * inv_freq;
    float c = cosf(ang), s = sinf(ang);

    size_t off = ((size_t)(b * T_ + t) * nh + h) * 64;
    float x1 = buf[off + i];
    float x2 = buf[off + 32 + i];
    buf[off + i]      = x1 * c - x2 * s;
    buf[off + 32 + i] = x2 * c + x1 * s;
}

// ---------------------------------------------------------------------------
// Flash-style causal attention, fp32, float4-vectorized smem reads.
// Grid: (T/64, H, B), Block: 64 threads; thread r owns query row qt*64+r.
// ---------------------------------------------------------------------------
__global__ __launch_bounds__(64)
void attn_kernel(float* __restrict__ Y, const float* __restrict__ Q,
                 const float* __restrict__ K, const float* __restrict__ V) {
    __shared__ float Ksh[64][64];
    __shared__ float Vsh[64][64];
    __shared__ float Ssh[64][64];

    const int r  = threadIdx.x;
    const int qt = blockIdx.x;
    const int h  = blockIdx.y;
    const int b  = blockIdx.z;
    const int kh = h >> 2;
    const int qi = qt * 64 + r;

    float4 q4[16];
    {
        const float4* qp = (const float4*)(Q + ((size_t)(b * T_ + qi) * H_ + h) * 64);
#pragma unroll
        for (int i = 0; i < 16; ++i) q4[i] = qp[i];
    }

    float4 o4[16];
#pragma unroll
    for (int i = 0; i < 16; ++i) o4[i] = make_float4(0.f, 0.f, 0.f, 0.f);
    float m = -1e30f, l = 0.0f;
    const float scale = 0.125f;

    for (int j = 0; j <= qt; ++j) {
        const float* Kt = K + (size_t)(b * T_ + j * 64) * (HKV_ * D_) + kh * 64;
        const float* Vt = V + (size_t)(b * T_ + j * 64) * (HKV_ * D_) + kh * 64;

        __syncthreads();
#pragma unroll
        for (int i = 0; i < 16; ++i) {
            int p = r + i * 64;
            int row = p >> 4, c4 = p & 15;
            *(float4*)&Ksh[row][c4 << 2] = *(const float4*)(Kt + (size_t)row * (HKV_ * D_) + (c4 << 2));
            *(float4*)&Vsh[row][c4 << 2] = *(const float4*)(Vt + (size_t)row * (HKV_ * D_) + (c4 << 2));
        }
        __syncthreads();

        const int smax = (j == qt) ? (r + 1) : 64;
        float tmax = -1e30f;

        for (int s = 0; s < 64; ++s) {
            const float4* K4 = (const float4*)&Ksh[s][0];
            float a0 = 0.f, a1 = 0.f, a2 = 0.f, a3 = 0.f;
#pragma unroll
            for (int i = 0; i < 16; ++i) {
                float4 kv = K4[i];
                a0 = fmaf(q4[i].x, kv.x, a0);
                a1 = fmaf(q4[i].y, kv.y, a1);
                a2 = fmaf(q4[i].z, kv.z, a2);
                a3 = fmaf(q4[i].w, kv.w, a3);
            }
            float sc = ((a0 + a1) + (a2 + a3)) * scale;
            if (s >= smax) sc = -1e30f;
            Ssh[s][r] = sc;
            tmax = fmaxf(tmax, sc);
        }

        float mnew = fmaxf(m, tmax);
        float corr = __expf(m - mnew);
        l *= corr;
#pragma unroll
        for (int i = 0; i < 16; ++i) {
            o4[i].x *= corr; o4[i].y *= corr; o4[i].z *= corr; o4[i].w *= corr;
        }

        for (int s = 0; s < 64; ++s) {
            float p = __expf(Ssh[s][r] - mnew);
            l += p;
            const float4* V4 = (const float4*)&Vsh[s][0];
#pragma unroll
            for (int i = 0; i < 16; ++i) {
                float4 vv = V4[i];
                o4[i].x = fmaf(p, vv.x, o4[i].x);
                o4[i].y = fmaf(p, vv.y, o4[i].y);
                o4[i].z = fmaf(p, vv.z, o4[i].z);
                o4[i].w = fmaf(p, vv.w, o4[i].w);
            }
        }
        m = mnew;
    }

    float inv = 1.0f / l;
    float* yrow = Y + ((size_t)(b * T_ + qi) * H_ + h) * 64;
#pragma unroll
    for (int i = 0; i < 16; ++i) {
        ((float4*)yrow)[i] = make_float4(o4[i].x * inv, o4[i].y * inv,
                                         o4[i].z * inv, o4[i].w * inv);
    }
}

// ---------------------------------------------------------------------------
// kernel_launch
// ---------------------------------------------------------------------------
extern "C" void kernel_launch(void* const* d_in, const int* in_sizes, int n_in,
                              void* d_out, int out_size) {
    const float* x  = (const float*)d_in[0];
    const float* Wq = (const float*)d_in[1];
    const float* Wk = (const float*)d_in[2];
    const float* Wv = (const float*)d_in[3];
    const float* Wo = (const float*)d_in[4];
    float* out = (float*)d_out;

    float *pQ, *pK, *pV, *pY;
    cudaGetSymbolAddress((void**)&pQ, g_Q);
    cudaGetSymbolAddress((void**)&pK, g_K);
    cudaGetSymbolAddress((void**)&pV, g_V);
    cudaGetSymbolAddress((void**)&pY, g_Y);
    __nv_bfloat16 *pxh, *pxl, *pYh, *pYl;
    __nv_bfloat16 *pWqh, *pWql, *pWkh, *pWkl, *pWvh, *pWvl, *pWoh, *pWol;
    cudaGetSymbolAddress((void**)&pxh, g_xh);   cudaGetSymbolAddress((void**)&pxl, g_xl);
    cudaGetSymbolAddress((void**)&pYh, g_Yh);   cudaGetSymbolAddress((void**)&pYl, g_Yl);
    cudaGetSymbolAddress((void**)&pWqh, g_Wqh); cudaGetSymbolAddress((void**)&pWql, g_Wql);
    cudaGetSymbolAddress((void**)&pWkh, g_Wkh); cudaGetSymbolAddress((void**)&pWkl, g_Wkl);
    cudaGetSymbolAddress((void**)&pWvh, g_Wvh); cudaGetSymbolAddress((void**)&pWvl, g_Wvl);
    cudaGetSymbolAddress((void**)&pWoh, g_Woh); cudaGetSymbolAddress((void**)&pWol, g_Wol);

    cudaFuncSetAttribute(gemm3_kernel, cudaFuncAttributeMaxDynamicSharedMemorySize,
                         GEMM_SMEM_TOTAL);

    // 1) split x
    {
        int n = BT_ * E_;
        split_kernel<<<(n + 255) / 256, 256>>>(x, pxh, pxl, n);
    }
    // 2) transpose+split weights
    tsplit_kernel<<<dim3((H_ * D_) / 32, E_ / 32), dim3(32, 8)>>>(Wq, pWqh, pWql, E_, H_ * D_);
    tsplit_kernel<<<dim3((HKV_ * D_) / 32, E_ / 32), dim3(32, 8)>>>(Wk, pWkh, pWkl, E_, HKV_ * D_);
    tsplit_kernel<<<dim3((HKV_ * D_) / 32, E_ / 32), dim3(32, 8)>>>(Wv, pWvh, pWvl, E_, HKV_ * D_);
    tsplit_kernel<<<dim3(E_ / 32, E_ / 32), dim3(32, 8)>>>(Wo, pWoh, pWol, E_, E_);

    // 3) QKV projections (mma.sync bf16x3)
    gemm3_kernel<<<dim3((H_ * D_) / 128, BT_ / 128), 256, GEMM_SMEM_TOTAL>>>(
        pQ, pxh, pxl, pWqh, pWql, BT_, H_ * D_, E_);
    gemm3_kernel<<<dim3((HKV_ * D_) / 128, BT_ / 128), 256, GEMM_SMEM_TOTAL>>>(
        pK, pxh, pxl, pWkh, pWkl, BT_, HKV_ * D_, E_);
    gemm3_kernel<<<dim3((HKV_ * D_) / 128, BT_ / 128), 256, GEMM_SMEM_TOTAL>>>(
        pV, pxh, pxl, pWvh, pWvl, BT_, HKV_ * D_, E_);

    // 4) RoPE
    {
        int nq = B_ * T_ * H_ * 32;
        rope_kernel<<<(nq + 255) / 256, 256>>>(pQ, H_);
        int nk = B_ * T_ * HKV_ * 32;
        rope_kernel<<<(nk + 255) / 256, 256>>>(pK, HKV_);
    }

    // 5) attention
    attn_kernel<<<dim3(T_ / 64, H_, B_), 64>>>(pY, pQ, pK, pV);

    // 6) split Y, output projection
    {
        int n = BT_ * E_;
        split_kernel<<<(n + 255) / 256, 256>>>(pY, pYh, pYl, n);
    }
    gemm3_kernel<<<dim3(E_ / 128, BT_ / 128), 256, GEMM_SMEM_TOTAL>>>(
        out, pYh, pYl, pWoh, pWol, BT_, E_, E_);
}

// round 4
// speedup vs baseline: 2.7849x; 1.7878x over previous
#include <cuda_runtime.h>
#include <cuda_bf16.h>
#include <cstdint>
#include <math.h>

// Problem constants
#define B_  2
#define T_  2048
#define E_  2048
#define H_  32
#define HKV_ 8
#define D_  64
#define BT_ (B_*T_)  // 4096

// ---------------------------------------------------------------------------
// Scratch (static device globals — allocation-free rule)
// ---------------------------------------------------------------------------
__device__ float g_Q[BT_ * H_ * D_];
__device__ float g_K[BT_ * HKV_ * D_];
__device__ float g_V[BT_ * HKV_ * D_];

__device__ __nv_bfloat16 g_xh[BT_ * E_],  g_xl[BT_ * E_];
__device__ __nv_bfloat16 g_Yh[BT_ * E_],  g_Yl[BT_ * E_];
__device__ __nv_bfloat16 g_Qh[BT_ * H_ * D_],   g_Ql[BT_ * H_ * D_];
__device__ __nv_bfloat16 g_Kh[BT_ * HKV_ * D_], g_Kl[BT_ * HKV_ * D_];
__device__ __nv_bfloat16 g_Vh[BT_ * HKV_ * D_], g_Vl[BT_ * HKV_ * D_];
// Transposed weights [N, K] split hi/lo
__device__ __nv_bfloat16 g_Wqh[E_ * H_ * D_],   g_Wql[E_ * H_ * D_];
__device__ __nv_bfloat16 g_Wkh[E_ * HKV_ * D_], g_Wkl[E_ * HKV_ * D_];
__device__ __nv_bfloat16 g_Wvh[E_ * HKV_ * D_], g_Wvl[E_ * HKV_ * D_];
__device__ __nv_bfloat16 g_Woh[E_ * E_],        g_Wol[E_ * E_];

// ---------------------------------------------------------------------------
// PTX helpers (sm_80+ path: mma.sync / ldmatrix / cp.async)
// ---------------------------------------------------------------------------
__device__ __forceinline__ uint32_t smem_u32(const void* p) {
    uint32_t a;
    asm("{ .reg .u64 t; cvta.to.shared.u64 t, %1; cvt.u32.u64 %0, t; }" : "=r"(a) : "l"(p));
    return a;
}

__device__ __forceinline__ void ldmx4(uint32_t* r, uint32_t addr) {
    asm volatile("ldmatrix.sync.aligned.m8n8.x4.shared.b16 {%0,%1,%2,%3}, [%4];"
                 : "=r"(r[0]), "=r"(r[1]), "=r"(r[2]), "=r"(r[3]) : "r"(addr));
}
__device__ __forceinline__ void ldmx4t(uint32_t* r, uint32_t addr) {
    asm volatile("ldmatrix.sync.aligned.m8n8.x4.trans.shared.b16 {%0,%1,%2,%3}, [%4];"
                 : "=r"(r[0]), "=r"(r[1]), "=r"(r[2]), "=r"(r[3]) : "r"(addr));
}

__device__ __forceinline__ void mma_bf16(float* acc, const uint32_t* a, const uint32_t b0,
                                         const uint32_t b1) {
    asm volatile(
        "mma.sync.aligned.m16n8k16.row.col.f32.bf16.bf16.f32 "
        "{%0,%1,%2,%3}, {%4,%5,%6,%7}, {%8,%9}, {%0,%1,%2,%3};"
        : "+f"(acc[0]), "+f"(acc[1]), "+f"(acc[2]), "+f"(acc[3])
        : "r"(a[0]), "r"(a[1]), "r"(a[2]), "r"(a[3]), "r"(b0), "r"(b1));
}

__device__ __forceinline__ void cp_async16(uint32_t saddr, const void* gaddr) {
    asm volatile("cp.async.cg.shared.global [%0], [%1], 16;" :: "r"(saddr), "l"(gaddr));
}
#define CP_COMMIT() asm volatile("cp.async.commit_group;" ::: "memory")
#define CP_WAIT(n)  asm volatile("cp.async.wait_group %0;" :: "n"(n) : "memory")

__device__ __forceinline__ uint32_t pack_bf16x2(float lo, float hi) {
    __nv_bfloat162 v = __floats2bfloat162_rn(lo, hi);
    return *reinterpret_cast<uint32_t*>(&v);
}

// ---------------------------------------------------------------------------
// bf16x3 split-precision GEMM via mma.sync (unchanged from round 3).
// ---------------------------------------------------------------------------
#define ROWB   80
#define REGB   (128 * ROWB)
#define BUFB   (4 * REGB)
#define GEMM_SMEM_TOTAL (2 * BUFB)

__device__ __forceinline__ void issue_buf(uint32_t sbuf,
                                          const __nv_bfloat16* ah, const __nv_bfloat16* al,
                                          const __nv_bfloat16* bh, const __nv_bfloat16* bl,
                                          int K, int tid) {
    const __nv_bfloat16* srcs[4] = {ah, al, bh, bl};
#pragma unroll
    for (int reg = 0; reg < 4; ++reg) {
        const __nv_bfloat16* s = srcs[reg];
        uint32_t sr = sbuf + reg * REGB;
#pragma unroll
        for (int j = 0; j < 2; ++j) {
            int c = tid + j * 256;
            int row = c >> 2, part = c & 3;
            cp_async16(sr + row * ROWB + part * 16, s + (size_t)row * K + part * 8);
        }
    }
}

__global__ __launch_bounds__(256)
void gemm3_kernel(float* __restrict__ C,
                  const __nv_bfloat16* __restrict__ Ah, const __nv_bfloat16* __restrict__ Al,
                  const __nv_bfloat16* __restrict__ Bh, const __nv_bfloat16* __restrict__ Bl,
                  int M, int N, int K) {
    extern __shared__ char smem[];
    const uint32_t sbase = smem_u32(smem);
    const int tid = threadIdx.x;
    const int wid = tid >> 5, lane = tid & 31;
    const int warp_m = wid >> 2;
    const int warp_n = wid & 3;
    const int bm = blockIdx.y * 128, bn = blockIdx.x * 128;

    const __nv_bfloat16* pAh = Ah + (size_t)bm * K;
    const __nv_bfloat16* pAl = Al + (size_t)bm * K;
    const __nv_bfloat16* pBh = Bh + (size_t)bn * K;
    const __nv_bfloat16* pBl = Bl + (size_t)bn * K;

    float acc[4][4][4];
#pragma unroll
    for (int i = 0; i < 4; ++i)
#pragma unroll
        for (int j = 0; j < 4; ++j)
#pragma unroll
            for (int k = 0; k < 4; ++k) acc[i][j][k] = 0.0f;

    const int NIT = K / 32;

    const uint32_t a_row = warp_m * 64 + (lane & 15);
    const uint32_t a_coff = (lane >> 4) * 16;
    const uint32_t b_rowbase = warp_n * 32 + (lane & 15);
    const uint32_t b_coff = (lane >> 4) * 16;

    issue_buf(sbase, pAh, pAl, pBh, pBl, K, tid);
    CP_COMMIT();

    for (int it = 0; it < NIT; ++it) {
        const uint32_t sbuf = sbase + (it & 1) * BUFB;
        if (it + 1 < NIT) {
            issue_buf(sbase + ((it + 1) & 1) * BUFB,
                      pAh + (it + 1) * 32, pAl + (it + 1) * 32,
                      pBh + (it + 1) * 32, pBl + (it + 1) * 32, K, tid);
            CP_COMMIT();
            CP_WAIT(1);
        } else {
            CP_WAIT(0);
        }
        __syncthreads();

        const uint32_t sAh = sbuf, sAl = sbuf + REGB;
        const uint32_t sBh = sbuf + 2 * REGB, sBl = sbuf + 3 * REGB;

#pragma unroll
        for (int ks = 0; ks < 2; ++ks) {
            const uint32_t kb = ks * 32;
            uint32_t bh[8], bl[8];
#pragma unroll
            for (int p = 0; p < 2; ++p) {
                uint32_t ba = (b_rowbase + p * 16) * ROWB + kb + b_coff;
                ldmx4(&bh[p * 4], sBh + ba);
                ldmx4(&bl[p * 4], sBl + ba);
            }
#pragma unroll
            for (int mi = 0; mi < 4; ++mi) {
                uint32_t aa = (a_row + mi * 16) * ROWB + kb + a_coff;
                uint32_t ah[4], al[4];
                ldmx4(ah, sAh + aa);
                ldmx4(al, sAl + aa);
#pragma unroll
                for (int ni = 0; ni < 4; ++ni) {
                    const int p = ni >> 1, q = ni & 1;
                    uint32_t b0h = bh[p * 4 + q], b1h = bh[p * 4 + q + 2];
                    uint32_t b0l = bl[p * 4 + q], b1l = bl[p * 4 + q + 2];
                    mma_bf16(acc[mi][ni], ah, b0h, b1h);
                    mma_bf16(acc[mi][ni], ah, b0l, b1l);
                    mma_bf16(acc[mi][ni], al, b0h, b1h);
                }
            }
        }
        __syncthreads();
    }

    const int rbase = bm + warp_m * 64 + (lane >> 2);
    const int cbase = bn + warp_n * 32 + (lane & 3) * 2;
#pragma unroll
    for (int mi = 0; mi < 4; ++mi) {
#pragma unroll
        for (int ni = 0; ni < 4; ++ni) {
            float* c0 = C + (size_t)(rbase + mi * 16) * N + cbase + ni * 8;
            float* c1 = C + (size_t)(rbase + mi * 16 + 8) * N + cbase + ni * 8;
            *(float2*)c0 = make_float2(acc[mi][ni][0], acc[mi][ni][1]);
            *(float2*)c1 = make_float2(acc[mi][ni][2], acc[mi][ni][3]);
        }
    }
}

// ---------------------------------------------------------------------------
// fp32 -> bf16 hi/lo split
// ---------------------------------------------------------------------------
__global__ __launch_bounds__(256)
void split_kernel(const float* __restrict__ in, __nv_bfloat16* __restrict__ hi,
                  __nv_bfloat16* __restrict__ lo, int n) {
    int i = blockIdx.x * blockDim.x + threadIdx.x;
    if (i >= n) return;
    float v = in[i];
    __nv_bfloat16 h = __float2bfloat16(v);
    hi[i] = h;
    lo[i] = __float2bfloat16(v - __bfloat162float(h));
}

// ---------------------------------------------------------------------------
// Transpose + split: W[K,N] fp32 -> Th/Tl[N,K] bf16
// ---------------------------------------------------------------------------
__global__ __launch_bounds__(256)
void tsplit_kernel(const float* __restrict__ W, __nv_bfloat16* __restrict__ Th,
                   __nv_bfloat16* __restrict__ Tl, int K, int N) {
    __shared__ float t[32][33];
    const int tx = threadIdx.x, ty = threadIdx.y;
    const int n0 = blockIdx.x * 32, k0 = blockIdx.y * 32;
#pragma unroll
    for (int i = 0; i < 4; ++i)
        t[ty + i * 8][tx] = W[(size_t)(k0 + ty + i * 8) * N + n0 + tx];
    __syncthreads();
#pragma unroll
    for (int i = 0; i < 4; ++i) {
        float v = t[tx][ty + i * 8];
        __nv_bfloat16 h = __float2bfloat16(v);
        size_t o = (size_t)(n0 + ty + i * 8) * K + k0 + tx;
        Th[o] = h;
        Tl[o] = __float2bfloat16(v - __bfloat162float(h));
    }
}

// ---------------------------------------------------------------------------
// RoPE + hi/lo split (fused): reads fp32, writes rotated bf16 hi/lo
// ---------------------------------------------------------------------------
__global__ __launch_bounds__(256)
void rope_split_kernel(const float* __restrict__ buf, __nv_bfloat16* __restrict__ hi,
                       __nv_bfloat16* __restrict__ lo, int nh) {
    int idx = blockIdx.x * blockDim.x + threadIdx.x;
    int total = B_ * T_ * nh * 32;
    if (idx >= total) return;
    int i = idx & 31;
    int h = (idx >> 5) % nh;
    int t = (idx / (32 * nh)) % T_;
    int b = idx / (32 * nh * T_);

    float inv_freq = expf(-(float)i * (9.210340371976184f / 32.0f));
    float ang = (float)t * inv_freq;
    float c = cosf(ang), s = sinf(ang);

    size_t off = ((size_t)(b * T_ + t) * nh + h) * 64;
    float x1 = buf[off + i];
    float x2 = buf[off + 32 + i];
    float r1 = x1 * c - x2 * s;
    float r2 = x2 * c + x1 * s;
    __nv_bfloat16 h1 = __float2bfloat16(r1);
    __nv_bfloat16 h2 = __float2bfloat16(r2);
    hi[off + i] = h1;              lo[off + i] = __float2bfloat16(r1 - __bfloat162float(h1));
    hi[off + 32 + i] = h2;         lo[off + 32 + i] = __float2bfloat16(r2 - __bfloat162float(h2));
}

// ---------------------------------------------------------------------------
// FA2-style causal attention with mma.sync, bf16x3 split precision.
// Grid (T/128, H, B), 256 threads (8 warps x 16 q-rows). Writes Yh/Yl bf16.
// ---------------------------------------------------------------------------
#define AROWB 144                       // 128B data + 16B pad (conflict-free ldmatrix)
#define KVREG (64 * AROWB)              // 9216
#define KVBUF (4 * KVREG)               // Kh,Kl,Vh,Vl = 36864
#define QREG  (128 * AROWB)             // 18432
#define ATT_SMEM (2 * QREG + 2 * KVBUF) // 110592

__global__ __launch_bounds__(256)
void attn_mma_kernel(__nv_bfloat16* __restrict__ Yh, __nv_bfloat16* __restrict__ Yl,
                     const __nv_bfloat16* __restrict__ Qh, const __nv_bfloat16* __restrict__ Ql,
                     const __nv_bfloat16* __restrict__ Kh, const __nv_bfloat16* __restrict__ Kl,
                     const __nv_bfloat16* __restrict__ Vh, const __nv_bfloat16* __restrict__ Vl) {
    extern __shared__ char smem[];
    const uint32_t sbase = smem_u32(smem);
    const uint32_t sQh = sbase, sQl = sbase + QREG;
    const uint32_t sKV = sbase + 2 * QREG;

    const int tid = threadIdx.x;
    const int wid = tid >> 5, lane = tid & 31;
    const int qb = blockIdx.x;          // 128-row q block
    const int h  = blockIdx.y;
    const int b  = blockIdx.z;
    const int kh = h >> 2;              // G = 4
    const int bT0 = b * T_;

    const int row0 = qb * 128 + wid * 16 + (lane >> 2);  // global q row
    const int row1 = row0 + 8;
    const int rowmin_w = qb * 128 + wid * 16;
    const int rowmax_w = rowmin_w + 15;

    // ---- issue Q tile loads (128 rows x 64 bf16, hi+lo) ----
    {
        const __nv_bfloat16* srcs[2] = {Qh, Ql};
#pragma unroll
        for (int j = 0; j < 8; ++j) {
            int c = tid + j * 256;
            int reg = c >> 10, idx = c & 1023;
            int row = idx >> 3, part = idx & 7;
            uint32_t dst = (reg ? sQl : sQh) + row * AROWB + part * 16;
            cp_async16(dst, srcs[reg] + ((size_t)(bT0 + qb * 128 + row) * H_ + h) * 64 + part * 8);
        }
    }
    // ---- issue KV tile 0 ----
    const __nv_bfloat16* kvsrc[4] = {Kh, Kl, Vh, Vl};
    {
#pragma unroll
        for (int j = 0; j < 8; ++j) {
            int c = tid + j * 256;
            int reg = c >> 9, idx = c & 511;
            int row = idx >> 3, part = idx & 7;
            uint32_t dst = sKV + reg * KVREG + row * AROWB + part * 16;
            cp_async16(dst, kvsrc[reg] + ((size_t)(bT0 + row) * HKV_ + kh) * 64 + part * 8);
        }
    }
    CP_COMMIT();
    CP_WAIT(0);
    __syncthreads();

    // ---- load Q fragments (scaled later via softmax scale on S) ----
    uint32_t qfh[4][4], qfl[4][4];
#pragma unroll
    for (int ks = 0; ks < 4; ++ks) {
        uint32_t qa = (wid * 16 + (lane & 15)) * AROWB + ks * 32 + (lane >> 4) * 16;
        ldmx4(qfh[ks], sQh + qa);
        ldmx4(qfl[ks], sQl + qa);
    }

    float o[8][4];
#pragma unroll
    for (int j = 0; j < 8; ++j)
#pragma unroll
        for (int k = 0; k < 4; ++k) o[j][k] = 0.0f;
    float m0 = -1e30f, m1 = -1e30f, l0 = 0.0f, l1 = 0.0f;
    const float scale = 0.125f;

    const int NT = 2 * qb + 2;
    for (int it = 0; it < NT; ++it) {
        if (it + 1 < NT) {
            uint32_t sb = sKV + ((it + 1) & 1) * KVBUF;
#pragma unroll
            for (int j = 0; j < 8; ++j) {
                int c = tid + j * 256;
                int reg = c >> 9, idx = c & 511;
                int row = idx >> 3, part = idx & 7;
                cp_async16(sb + reg * KVREG + row * AROWB + part * 16,
                           kvsrc[reg] + ((size_t)(bT0 + (it + 1) * 64 + row) * HKV_ + kh) * 64 + part * 8);
            }
            CP_COMMIT();
            CP_WAIT(1);
        } else {
            CP_WAIT(0);
        }
        __syncthreads();

        const int kt = it;
        if (kt * 64 <= rowmax_w) {
            const uint32_t sb = sKV + (it & 1) * KVBUF;
            const uint32_t sKh = sb, sKl = sb + KVREG;
            const uint32_t sVh = sb + 2 * KVREG, sVl = sb + 3 * KVREG;

            // ---- S = scale * (Qh Kh + Qh Kl + Ql Kh) ----
            float s[8][4];
#pragma unroll
            for (int j = 0; j < 8; ++j)
#pragma unroll
                for (int k = 0; k < 4; ++k) s[j][k] = 0.0f;

#pragma unroll
            for (int ks = 0; ks < 4; ++ks) {
#pragma unroll
                for (int pg = 0; pg < 2; ++pg) {
                    uint32_t kfh[2][4], kfl[2][4];
#pragma unroll
                    for (int pp = 0; pp < 2; ++pp) {
                        uint32_t ka = ((2 * pg + pp) * 16 + (lane & 15)) * AROWB + ks * 32 + (lane >> 4) * 16;
                        ldmx4(kfh[pp], sKh + ka);
                        ldmx4(kfl[pp], sKl + ka);
                    }
                    // term 0: Qh*Kh over 4 accs, then Qh*Kl, then Ql*Kh (ILP-friendly)
#pragma unroll
                    for (int pp = 0; pp < 2; ++pp)
#pragma unroll
                        for (int q = 0; q < 2; ++q)
                            mma_bf16(s[(2 * pg + pp) * 2 + q], qfh[ks], kfh[pp][q], kfh[pp][q + 2]);
#pragma unroll
                    for (int pp = 0; pp < 2; ++pp)
#pragma unroll
                        for (int q = 0; q < 2; ++q)
                            mma_bf16(s[(2 * pg + pp) * 2 + q], qfh[ks], kfl[pp][q], kfl[pp][q + 2]);
#pragma unroll
                    for (int pp = 0; pp < 2; ++pp)
#pragma unroll
                        for (int q = 0; q < 2; ++q)
                            mma_bf16(s[(2 * pg + pp) * 2 + q], qfl[ks], kfh[pp][q], kfh[pp][q + 2]);
                }
            }

            // ---- scale + causal mask ----
            const bool needs_mask = (kt * 64 + 63) > rowmin_w;
#pragma unroll
            for (int j = 0; j < 8; ++j) {
#pragma unroll
                for (int k = 0; k < 4; ++k) s[j][k] *= scale;
                if (needs_mask) {
                    int colb = kt * 64 + j * 8 + 2 * (lane & 3);
                    if (colb > row0)     s[j][0] = -1e30f;
                    if (colb + 1 > row0) s[j][1] = -1e30f;
                    if (colb > row1)     s[j][2] = -1e30f;
                    if (colb + 1 > row1) s[j][3] = -1e30f;
                }
            }

            // ---- online softmax ----
            float mx0 = -1e30f, mx1 = -1e30f;
#pragma unroll
            for (int j = 0; j < 8; ++j) {
                mx0 = fmaxf(mx0, fmaxf(s[j][0], s[j][1]));
                mx1 = fmaxf(mx1, fmaxf(s[j][2], s[j][3]));
            }
            mx0 = fmaxf(mx0, __shfl_xor_sync(0xFFFFFFFF, mx0, 1));
            mx0 = fmaxf(mx0, __shfl_xor_sync(0xFFFFFFFF, mx0, 2));
            mx1 = fmaxf(mx1, __shfl_xor_sync(0xFFFFFFFF, mx1, 1));
            mx1 = fmaxf(mx1, __shfl_xor_sync(0xFFFFFFFF, mx1, 2));

            float mn0 = fmaxf(m0, mx0), mn1 = fmaxf(m1, mx1);
            float c0 = __expf(m0 - mn0), c1 = __expf(m1 - mn1);
            m0 = mn0; m1 = mn1;
            l0 *= c0; l1 *= c1;
#pragma unroll
            for (int j = 0; j < 8; ++j) {
                o[j][0] *= c0; o[j][1] *= c0; o[j][2] *= c1; o[j][3] *= c1;
            }
#pragma unroll
            for (int j = 0; j < 8; ++j) {
                s[j][0] = __expf(s[j][0] - mn0);
                s[j][1] = __expf(s[j][1] - mn0);
                s[j][2] = __expf(s[j][2] - mn1);
                s[j][3] = __expf(s[j][3] - mn1);
                l0 += s[j][0] + s[j][1];
                l1 += s[j][2] + s[j][3];
            }

            // ---- O += (Ph + Pl) V: 3 terms ----
#pragma unroll
            for (int ks = 0; ks < 4; ++ks) {
                // P A-fragment for key-kstep ks from S C-frags 2ks, 2ks+1
                uint32_t pah[4], pal[4];
                {
                    float p00 = s[2 * ks][0], p01 = s[2 * ks][1];
                    float p02 = s[2 * ks][2], p03 = s[2 * ks][3];
                    float p10 = s[2 * ks + 1][0], p11 = s[2 * ks + 1][1];
                    float p12 = s[2 * ks + 1][2], p13 = s[2 * ks + 1][3];
                    pah[0] = pack_bf16x2(p00, p01);
                    pah[1] = pack_bf16x2(p02, p03);
                    pah[2] = pack_bf16x2(p10, p11);
                    pah[3] = pack_bf16x2(p12, p13);
                    __nv_bfloat162 h0 = *reinterpret_cast<__nv_bfloat162*>(&pah[0]);
                    __nv_bfloat162 h1 = *reinterpret_cast<__nv_bfloat162*>(&pah[1]);
                    __nv_bfloat162 h2 = *reinterpret_cast<__nv_bfloat162*>(&pah[2]);
                    __nv_bfloat162 h3 = *reinterpret_cast<__nv_bfloat162*>(&pah[3]);
                    pal[0] = pack_bf16x2(p00 - __low2float(h0), p01 - __high2float(h0));
                    pal[1] = pack_bf16x2(p02 - __low2float(h1), p03 - __high2float(h1));
                    pal[2] = pack_bf16x2(p10 - __low2float(h2), p11 - __high2float(h2));
                    pal[3] = pack_bf16x2(p12 - __low2float(h3), p13 - __high2float(h3));
                }
#pragma unroll
                for (int pg = 0; pg < 2; ++pg) {
                    uint32_t vfh[2][4], vfl[2][4];
#pragma unroll
                    for (int pp = 0; pp < 2; ++pp) {
                        uint32_t va = (ks * 16 + (lane & 15)) * AROWB + (2 * pg + pp) * 32 + (lane >> 4) * 16;
                        ldmx4t(vfh[pp], sVh + va);
                        ldmx4t(vfl[pp], sVl + va);
                    }
#pragma unroll
                    for (int pp = 0; pp < 2; ++pp)
#pragma unroll
                        for (int q = 0; q < 2; ++q)
                            mma_bf16(o[(2 * pg + pp) * 2 + q], pah, vfh[pp][2 * q], vfh[pp][2 * q + 1]);
#pragma unroll
                    for (int pp = 0; pp < 2; ++pp)
#pragma unroll
                        for (int q = 0; q < 2; ++q)
                            mma_bf16(o[(2 * pg + pp) * 2 + q], pal, vfh[pp][2 * q], vfh[pp][2 * q + 1]);
#pragma unroll
                    for (int pp = 0; pp < 2; ++pp)
#pragma unroll
                        for (int q = 0; q < 2; ++q)
                            mma_bf16(o[(2 * pg + pp) * 2 + q], pah, vfl[pp][2 * q], vfl[pp][2 * q + 1]);
                }
            }
        }
        __syncthreads();
    }

    // ---- finalize: full row sums, normalize, write Yh/Yl ----
    l0 += __shfl_xor_sync(0xFFFFFFFF, l0, 1);
    l0 += __shfl_xor_sync(0xFFFFFFFF, l0, 2);
    l1 += __shfl_xor_sync(0xFFFFFFFF, l1, 1);
    l1 += __shfl_xor_sync(0xFFFFFFFF, l1, 2);
    float inv0 = 1.0f / l0, inv1 = 1.0f / l1;

#pragma unroll
    for (int j = 0; j < 8; ++j) {
        int col = j * 8 + 2 * (lane & 3);
        float y0 = o[j][0] * inv0, y1 = o[j][1] * inv0;
        float y2 = o[j][2] * inv1, y3 = o[j][3] * inv1;
        size_t a0 = ((size_t)(bT0 + row0) * H_ + h) * 64 + col;
        size_t a1 = ((size_t)(bT0 + row1) * H_ + h) * 64 + col;
        uint32_t h01 = pack_bf16x2(y0, y1);
        uint32_t h23 = pack_bf16x2(y2, y3);
        __nv_bfloat162 hb01 = *reinterpret_cast<__nv_bfloat162*>(&h01);
        __nv_bfloat162 hb23 = *reinterpret_cast<__nv_bfloat162*>(&h23);
        uint32_t l01 = pack_bf16x2(y0 - __low2float(hb01), y1 - __high2float(hb01));
        uint32_t l23 = pack_bf16x2(y2 - __low2float(hb23), y3 - __high2float(hb23));
        *(uint32_t*)&Yh[a0] = h01;
        *(uint32_t*)&Yh[a1] = h23;
        *(uint32_t*)&Yl[a0] = l01;
        *(uint32_t*)&Yl[a1] = l23;
    }
}

// ---------------------------------------------------------------------------
// kernel_launch
// ---------------------------------------------------------------------------
extern "C" void kernel_launch(void* const* d_in, const int* in_sizes, int n_in,
                              void* d_out, int out_size) {
    const float* x  = (const float*)d_in[0];
    const float* Wq = (const float*)d_in[1];
    const float* Wk = (const float*)d_in[2];
    const float* Wv = (const float*)d_in[3];
    const float* Wo = (const float*)d_in[4];
    float* out = (float*)d_out;

    float *pQ, *pK, *pV;
    cudaGetSymbolAddress((void**)&pQ, g_Q);
    cudaGetSymbolAddress((void**)&pK, g_K);
    cudaGetSymbolAddress((void**)&pV, g_V);
    __nv_bfloat16 *pxh, *pxl, *pYh, *pYl;
    __nv_bfloat16 *pQh, *pQl, *pKh, *pKl, *pVh, *pVl;
    __nv_bfloat16 *pWqh, *pWql, *pWkh, *pWkl, *pWvh, *pWvl, *pWoh, *pWol;
    cudaGetSymbolAddress((void**)&pxh, g_xh);   cudaGetSymbolAddress((void**)&pxl, g_xl);
    cudaGetSymbolAddress((void**)&pYh, g_Yh);   cudaGetSymbolAddress((void**)&pYl, g_Yl);
    cudaGetSymbolAddress((void**)&pQh, g_Qh);   cudaGetSymbolAddress((void**)&pQl, g_Ql);
    cudaGetSymbolAddress((void**)&pKh, g_Kh);   cudaGetSymbolAddress((void**)&pKl, g_Kl);
    cudaGetSymbolAddress((void**)&pVh, g_Vh);   cudaGetSymbolAddress((void**)&pVl, g_Vl);
    cudaGetSymbolAddress((void**)&pWqh, g_Wqh); cudaGetSymbolAddress((void**)&pWql, g_Wql);
    cudaGetSymbolAddress((void**)&pWkh, g_Wkh); cudaGetSymbolAddress((void**)&pWkl, g_Wkl);
    cudaGetSymbolAddress((void**)&pWvh, g_Wvh); cudaGetSymbolAddress((void**)&pWvl, g_Wvl);
    cudaGetSymbolAddress((void**)&pWoh, g_Woh); cudaGetSymbolAddress((void**)&pWol, g_Wol);

    cudaFuncSetAttribute(gemm3_kernel, cudaFuncAttributeMaxDynamicSharedMemorySize,
                         GEMM_SMEM_TOTAL);
    cudaFuncSetAttribute(attn_mma_kernel, cudaFuncAttributeMaxDynamicSharedMemorySize,
                         ATT_SMEM);

    // 1) split x
    {
        int n = BT_ * E_;
        split_kernel<<<(n + 255) / 256, 256>>>(x, pxh, pxl, n);
    }
    // 2) transpose+split weights
    tsplit_kernel<<<dim3((H_ * D_) / 32, E_ / 32), dim3(32, 8)>>>(Wq, pWqh, pWql, E_, H_ * D_);
    tsplit_kernel<<<dim3((HKV_ * D_) / 32, E_ / 32), dim3(32, 8)>>>(Wk, pWkh, pWkl, E_, HKV_ * D_);
    tsplit_kernel<<<dim3((HKV_ * D_) / 32, E_ / 32), dim3(32, 8)>>>(Wv, pWvh, pWvl, E_, HKV_ * D_);
    tsplit_kernel<<<dim3(E_ / 32, E_ / 32), dim3(32, 8)>>>(Wo, pWoh, pWol, E_, E_);

    // 3) QKV projections (mma.sync bf16x3)
    gemm3_kernel<<<dim3((H_ * D_) / 128, BT_ / 128), 256, GEMM_SMEM_TOTAL>>>(
        pQ, pxh, pxl, pWqh, pWql, BT_, H_ * D_, E_);
    gemm3_kernel<<<dim3((HKV_ * D_) / 128, BT_ / 128), 256, GEMM_SMEM_TOTAL>>>(
        pK, pxh, pxl, pWkh, pWkl, BT_, HKV_ * D_, E_);
    gemm3_kernel<<<dim3((HKV_ * D_) / 128, BT_ / 128), 256, GEMM_SMEM_TOTAL>>>(
        pV, pxh, pxl, pWvh, pWvl, BT_, HKV_ * D_, E_);

    // 4) RoPE + split Q,K; split V
    {
        int nq = B_ * T_ * H_ * 32;
        rope_split_kernel<<<(nq + 255) / 256, 256>>>(pQ, pQh, pQl, H_);
        int nk = B_ * T_ * HKV_ * 32;
        rope_split_kernel<<<(nk + 255) / 256, 256>>>(pK, pKh, pKl, HKV_);
        int nv = BT_ * HKV_ * D_;
        split_kernel<<<(nv + 255) / 256, 256>>>(pV, pVh, pVl, nv);
    }

    // 5) attention (mma.sync, writes Yh/Yl directly)
    attn_mma_kernel<<<dim3(T_ / 128, H_, B_), 256, ATT_SMEM>>>(
        pYh, pYl, pQh, pQl, pKh, pKl, pVh, pVl);

    // 6) output projection
    gemm3_kernel<<<dim3(E_ / 128, BT_ / 128), 256, GEMM_SMEM_TOTAL>>>(
        out, pYh, pYl, pWoh, pWol, BT_, E_, E_);
}